// round 1
// baseline (speedup 1.0000x reference)
#include <cuda_runtime.h>
#include <math.h>

#define Hh    768
#define NB    32
#define NS    1024
#define NF    128
#define NP    256
#define NROWS (NB * NF)          // 4096

// output segment offsets (floats), concatenated in reference return order
#define OFF_MSR   0              // (B,F,2)  8192
#define OFF_AGG   8192           // (B,F,9)  36864
#define OFF_MSRS  45056          // (B,F,2)  8192   (msr_score_res = W_msrs head)
#define OFF_DIM   53248          // (B,F,2)  8192
#define OFF_KEY   61440          // (B,F,2)  8192
#define OFF_PAIR  69632          // (B,P,2)  16384
#define OFF_TYPE  86016          // (B,F,7)  28672
// total = 114688

__device__ float g_field[NROWS * Hh];  // field_embedding scratch (12.6 MB)
__device__ float g_u[NROWS * 4];       // pair partial dots: {u1_c0,u1_c1,u2_c0,u2_c1}

// ---------------------------------------------------------------------------
// K1: scatter-mean. One block per (field f, batch b). Warp 0 builds an ordered
// match list via ballot scan; 192 threads each own one float4 slice of H.
// ---------------------------------------------------------------------------
__global__ __launch_bounds__(192) void k1_scatter_mean(
    const float* __restrict__ emb, const int* __restrict__ col_ids)
{
    __shared__ int sList[NS];
    __shared__ int sCnt;
    const int f   = blockIdx.x;
    const int b   = blockIdx.y;
    const int tid = threadIdx.x;

    if (tid < 32) {
        int cnt = 0;
        const int target = f + 1;               // segment 0 = dropped tokens
        const int* crow = col_ids + b * NS;
        for (int base = 0; base < NS; base += 32) {
            int c = crow[base + tid];
            unsigned m = __ballot_sync(0xffffffffu, c == target);
            if (c == target)
                sList[cnt + __popc(m & ((1u << tid) - 1u))] = base + tid;
            cnt += __popc(m);
        }
        if (tid == 0) sCnt = cnt;
    }
    __syncthreads();

    const int n = sCnt;
    const float4* base = (const float4*)(emb + (size_t)b * NS * Hh) + tid;
    float4 a0 = make_float4(0.f, 0.f, 0.f, 0.f);
    float4 a1 = make_float4(0.f, 0.f, 0.f, 0.f);
    int i = 0;
    for (; i + 1 < n; i += 2) {
        float4 v0 = base[sList[i]     * (Hh / 4)];
        float4 v1 = base[sList[i + 1] * (Hh / 4)];
        a0.x += v0.x; a0.y += v0.y; a0.z += v0.z; a0.w += v0.w;
        a1.x += v1.x; a1.y += v1.y; a1.z += v1.z; a1.w += v1.w;
    }
    if (i < n) {
        float4 v0 = base[sList[i] * (Hh / 4)];
        a0.x += v0.x; a0.y += v0.y; a0.z += v0.z; a0.w += v0.w;
    }
    const float inv = 1.0f / (float)(n > 0 ? n : 1);
    float4 r;
    r.x = (a0.x + a1.x) * inv;
    r.y = (a0.y + a1.y) * inv;
    r.z = (a0.z + a1.z) * inv;
    r.w = (a0.w + a1.w) * inv;
    ((float4*)(g_field + (size_t)(b * NF + f) * Hh))[tid] = r;
}

// ---------------------------------------------------------------------------
// K2: heads GEMM (4096 x 768) x (768 x 28->pad32) fused with log_softmax.
// Class layout: [0:2)=msr [2:11)=agg [11:13)=dim [13:15)=msrs [15:17)=key
//               [17:24)=type [24:26)=u1(pair top) [26:28)=u2(pair bottom)
// One block per 32 field rows. W^T + V tile in shared. Thread = (rg,cg,kq):
// 4 rows x 4 classes x quarter-of-k, kq reduced via shfl_xor.
// ---------------------------------------------------------------------------
#define TILE 32
#define NCP  32
#define WS   772   // padded row stride in floats (768 + 4)

__device__ __forceinline__ void write_lsm(float* dst, const float* l, int n)
{
    float m = l[0];
    for (int i = 1; i < n; i++) m = fmaxf(m, l[i]);
    float s = 0.f;
    for (int i = 0; i < n; i++) s += expf(l[i] - m);
    const float lse = m + logf(s);
    for (int i = 0; i < n; i++) dst[i] = l[i] - lse;
}

__global__ __launch_bounds__(256) void k2_heads(
    const float* __restrict__ Wmsr,  const float* __restrict__ bmsr,
    const float* __restrict__ Wagg,  const float* __restrict__ bagg,
    const float* __restrict__ Wdim,  const float* __restrict__ bdim,
    const float* __restrict__ Wmsrs, const float* __restrict__ bmsrs,
    const float* __restrict__ Wkey,  const float* __restrict__ bkey,
    const float* __restrict__ Wpair, const float* __restrict__ Wtype,
    const float* __restrict__ btype,
    float* __restrict__ out)
{
    extern __shared__ float sh[];
    float* sWt = sh;              // [NCP][WS] : W transposed, class-major
    float* sV  = sh + NCP * WS;   // [TILE][WS]
    __shared__ float sLog[TILE][NCP];
    __shared__ float sB[NCP];

    const int tid  = threadIdx.x;
    const int nt   = blockDim.x;   // 256
    const int row0 = blockIdx.x * TILE;

    // ---- stage W^T ----
    for (int i = tid; i < Hh * 2; i += nt) { int h = i >> 1, c = i & 1;  sWt[(0  + c) * WS + h] = Wmsr[i]; }
    for (int i = tid; i < Hh * 9; i += nt) { int h = i / 9, c = i - h * 9; sWt[(2  + c) * WS + h] = Wagg[i]; }
    for (int i = tid; i < Hh * 2; i += nt) { int h = i >> 1, c = i & 1;  sWt[(11 + c) * WS + h] = Wdim[i]; }
    for (int i = tid; i < Hh * 2; i += nt) { int h = i >> 1, c = i & 1;  sWt[(13 + c) * WS + h] = Wmsrs[i]; }
    for (int i = tid; i < Hh * 2; i += nt) { int h = i >> 1, c = i & 1;  sWt[(15 + c) * WS + h] = Wkey[i]; }
    for (int i = tid; i < Hh * 7; i += nt) { int h = i / 7, c = i - h * 7; sWt[(17 + c) * WS + h] = Wtype[i]; }
    for (int i = tid; i < Hh * 2; i += nt) {
        int h = i >> 1, c = i & 1;
        sWt[(24 + c) * WS + h] = Wpair[i];                    // W_pair[0:H, c]
        sWt[(26 + c) * WS + h] = Wpair[(Hh + h) * 2 + c];     // W_pair[H:2H, c]
    }
    for (int i = tid; i < Hh * 4; i += nt) { int h = i >> 2, c = i & 3; sWt[(28 + c) * WS + h] = 0.f; }

    if (tid < NCP) {
        float bv = 0.f;
        if      (tid < 2)  bv = bmsr[tid];
        else if (tid < 11) bv = bagg[tid - 2];
        else if (tid < 13) bv = bdim[tid - 11];
        else if (tid < 15) bv = bmsrs[tid - 13];
        else if (tid < 17) bv = bkey[tid - 15];
        else if (tid < 24) bv = btype[tid - 17];
        sB[tid] = bv;                    // pair bias added in K3
    }

    // ---- stage V tile ----
    for (int i = tid; i < TILE * (Hh / 4); i += nt) {
        int r = i / (Hh / 4), c4 = i - r * (Hh / 4);
        float4 v = ((const float4*)(g_field + (size_t)(row0 + r) * Hh))[c4];
        *((float4*)(sV + r * WS + c4 * 4)) = v;
    }
    __syncthreads();

    // ---- compute ----
    const int kq = tid & 3;
    const int cg = (tid >> 2) & 7;
    const int rg = tid >> 5;

    float acc[4][4];
#pragma unroll
    for (int a = 0; a < 4; a++)
#pragma unroll
        for (int c = 0; c < 4; c++) acc[a][c] = 0.f;

    const float* v0 = sV + (rg * 4 + 0) * WS;
    const float* v1 = sV + (rg * 4 + 1) * WS;
    const float* v2 = sV + (rg * 4 + 2) * WS;
    const float* v3 = sV + (rg * 4 + 3) * WS;
    const float* w0 = sWt + (cg * 4 + 0) * WS;
    const float* w1 = sWt + (cg * 4 + 1) * WS;
    const float* w2 = sWt + (cg * 4 + 2) * WS;
    const float* w3 = sWt + (cg * 4 + 3) * WS;

#pragma unroll 4
    for (int j = kq; j < Hh / 4; j += 4) {
        const int k = j * 4;
        float4 p0 = *(const float4*)(v0 + k);
        float4 p1 = *(const float4*)(v1 + k);
        float4 p2 = *(const float4*)(v2 + k);
        float4 p3 = *(const float4*)(v3 + k);
        float4 q0 = *(const float4*)(w0 + k);
        float4 q1 = *(const float4*)(w1 + k);
        float4 q2 = *(const float4*)(w2 + k);
        float4 q3 = *(const float4*)(w3 + k);
#define FMA4(R, P, C, Q) \
        acc[R][C] += P.x * Q.x + P.y * Q.y + P.z * Q.z + P.w * Q.w;
        FMA4(0, p0, 0, q0) FMA4(0, p0, 1, q1) FMA4(0, p0, 2, q2) FMA4(0, p0, 3, q3)
        FMA4(1, p1, 0, q0) FMA4(1, p1, 1, q1) FMA4(1, p1, 2, q2) FMA4(1, p1, 3, q3)
        FMA4(2, p2, 0, q0) FMA4(2, p2, 1, q1) FMA4(2, p2, 2, q2) FMA4(2, p2, 3, q3)
        FMA4(3, p3, 0, q0) FMA4(3, p3, 1, q1) FMA4(3, p3, 2, q2) FMA4(3, p3, 3, q3)
#undef FMA4
    }

    // reduce 4-way k-split (kq lives in lane bits 0-1)
#pragma unroll
    for (int a = 0; a < 4; a++)
#pragma unroll
        for (int c = 0; c < 4; c++) {
            float v = acc[a][c];
            v += __shfl_xor_sync(0xffffffffu, v, 1);
            v += __shfl_xor_sync(0xffffffffu, v, 2);
            acc[a][c] = v;
        }
    if (kq == 0) {
#pragma unroll
        for (int a = 0; a < 4; a++)
#pragma unroll
            for (int c = 0; c < 4; c++)
                sLog[rg * 4 + a][cg * 4 + c] = acc[a][c];
    }
    __syncthreads();

    // ---- per-row log_softmax + writes ----
    if (tid < TILE) {
        const int row = row0 + tid;
        float l[28];
#pragma unroll
        for (int c = 0; c < 28; c++) l[c] = sLog[tid][c] + sB[c];

        write_lsm(out + OFF_MSR  + row * 2, l + 0,  2);
        write_lsm(out + OFF_AGG  + row * 9, l + 2,  9);
        write_lsm(out + OFF_MSRS + row * 2, l + 13, 2);
        write_lsm(out + OFF_DIM  + row * 2, l + 11, 2);
        write_lsm(out + OFF_KEY  + row * 2, l + 15, 2);
        write_lsm(out + OFF_TYPE + row * 7, l + 17, 7);

        float* u = g_u + row * 4;   // pair partials (no bias)
        u[0] = l[24]; u[1] = l[25]; u[2] = l[26]; u[3] = l[27];
    }
}

// ---------------------------------------------------------------------------
// K3: pair head from precomputed partial dots. One thread per (b, p).
// ---------------------------------------------------------------------------
__global__ __launch_bounds__(256) void k3_pair(
    const int* __restrict__ pidx, const float* __restrict__ bpair,
    float* __restrict__ out)
{
    const int p = blockIdx.x * blockDim.x + threadIdx.x;   // 0 .. B*P-1
    if (p >= NB * NP) return;
    const int b  = p >> 8;                                 // p / NP
    const int i1 = pidx[2 * p];
    const int i2 = pidx[2 * p + 1];
    const float* u1 = g_u + (size_t)(b * NF + i1) * 4;
    const float* u2 = g_u + (size_t)(b * NF + i2) * 4;
    const float l0 = u1[0] + u2[2] + bpair[0];
    const float l1 = u1[1] + u2[3] + bpair[1];
    const float m  = fmaxf(l0, l1);
    const float lse = m + logf(expf(l0 - m) + expf(l1 - m));
    out[OFF_PAIR + 2 * p]     = l0 - lse;
    out[OFF_PAIR + 2 * p + 1] = l1 - lse;
}

// ---------------------------------------------------------------------------
extern "C" void kernel_launch(void* const* d_in, const int* in_sizes, int n_in,
                              void* d_out, int out_size)
{
    const float* emb  = (const float*)d_in[0];
    const int*   col  = (const int*)d_in[1];
    const int*   pidx = (const int*)d_in[2];
    // weights occupy the last 14 slots (n_fields scalar may or may not be an input)
    const int wb = n_in - 14;
    const float* Wmsr  = (const float*)d_in[wb + 0];
    const float* bmsr  = (const float*)d_in[wb + 1];
    const float* Wagg  = (const float*)d_in[wb + 2];
    const float* bagg  = (const float*)d_in[wb + 3];
    const float* Wdim  = (const float*)d_in[wb + 4];
    const float* bdim  = (const float*)d_in[wb + 5];
    const float* Wmsrs = (const float*)d_in[wb + 6];
    const float* bmsrs = (const float*)d_in[wb + 7];
    const float* Wkey  = (const float*)d_in[wb + 8];
    const float* bkey  = (const float*)d_in[wb + 9];
    const float* Wpair = (const float*)d_in[wb + 10];
    const float* bpair = (const float*)d_in[wb + 11];
    const float* Wtype = (const float*)d_in[wb + 12];
    const float* btype = (const float*)d_in[wb + 13];
    float* out = (float*)d_out;

    k1_scatter_mean<<<dim3(NF, NB), 192>>>(emb, col);

    const int shmem = (NCP + TILE) * WS * (int)sizeof(float);  // 197,632 B
    cudaFuncSetAttribute(k2_heads, cudaFuncAttributeMaxDynamicSharedMemorySize, shmem);
    k2_heads<<<NROWS / TILE, 256, shmem>>>(Wmsr, bmsr, Wagg, bagg, Wdim, bdim,
                                           Wmsrs, bmsrs, Wkey, bkey,
                                           Wpair, Wtype, btype, out);

    k3_pair<<<(NB * NP) / 256, 256>>>(pidx, bpair, out);
}